// round 2
// baseline (speedup 1.0000x reference)
#include <cuda_runtime.h>
#include <math.h>

#define B_ 8
#define H_ 256
#define W_ 256
#define C_ 128
#define HW_ (H_ * W_)          // 65536
#define P_ (B_ * HW_)          // 524288 pixels
#define NBLK_ 128              // reduction chunks per batch
#define PIX_PER_CHUNK_ (HW_ / NBLK_)   // 512
#define THRESH_ 0.8f
#define EPS_ 1e-3f

// ---- scratch (device globals; no allocation allowed) ----
__device__ float g_pooled[P_ * 2];                 // [pixel][2] = {max, avg}   4 MB
__device__ float g_xmap[P_];                       // sigmoid map               2 MB
__device__ float g_gmap[P_];                       // gamma map                 2 MB
__device__ float g_bmap[P_];                       // beta map                  2 MB
__device__ unsigned char g_mask[P_];               // region mask               0.5 MB
__device__ int   g_counts[B_];                     // mask count per batch
__device__ float4 g_partials[B_ * NBLK_ * C_];     // {s1v,s2v,s1,s2}           2 MB
__device__ float g_params[B_ * 2 * C_ * 2];        // [b][region][c][{mu,istd}] 8 KB

// ============================================================
// Kernel 1: channel max/avg pool. One warp per pixel.
// ============================================================
__global__ void pool_kernel(const float* __restrict__ in) {
    int gw = (blockIdx.x * blockDim.x + threadIdx.x) >> 5;   // pixel id
    int lane = threadIdx.x & 31;
    const float4* p = (const float4*)(in + (size_t)gw * C_);
    float4 v = p[lane];
    float mx = fmaxf(fmaxf(v.x, v.y), fmaxf(v.z, v.w));
    float sm = (v.x + v.y) + (v.z + v.w);
    #pragma unroll
    for (int o = 16; o; o >>= 1) {
        mx = fmaxf(mx, __shfl_xor_sync(0xFFFFFFFFu, mx, o));
        sm += __shfl_xor_sync(0xFFFFFFFFu, sm, o);
    }
    if (lane == 0) {
        float2 r; r.x = mx; r.y = sm * (1.0f / (float)C_);
        ((float2*)g_pooled)[gw] = r;
    }
}

// ============================================================
// Kernel 2: 3x3 conv (2ch -> 1ch) + sigmoid
// ============================================================
__global__ void conv_sr_kernel(const float* __restrict__ w_sr,
                               const float* __restrict__ b_sr) {
    int p = blockIdx.x * blockDim.x + threadIdx.x;
    if (p >= P_) return;
    int b  = p >> 16;
    int hw = p & (HW_ - 1);
    int h  = hw >> 8;
    int w  = hw & (W_ - 1);
    float acc = b_sr[0];
    #pragma unroll
    for (int kh = 0; kh < 3; kh++) {
        int hh = h + kh - 1;
        if (hh < 0 || hh >= H_) continue;
        #pragma unroll
        for (int kw = 0; kw < 3; kw++) {
            int ww = w + kw - 1;
            if (ww < 0 || ww >= W_) continue;
            int q = (b << 16) | (hh << 8) | ww;
            float2 pv = ((const float2*)g_pooled)[q];
            acc += pv.x * w_sr[(kh * 3 + kw) * 2] + pv.y * w_sr[(kh * 3 + kw) * 2 + 1];
        }
    }
    g_xmap[p] = 1.0f / (1.0f + expf(-acc));
}

// ============================================================
// Kernel 2b: zero the per-batch counts
// ============================================================
__global__ void zero_counts_kernel() {
    if (threadIdx.x < B_) g_counts[threadIdx.x] = 0;
}

// ============================================================
// Kernel 3: gamma/beta 3x3 convs on xmap + mask + per-batch count
// (each 256-thread block lies entirely within one batch)
// ============================================================
__global__ void conv_gb_kernel(const float* __restrict__ w_g,
                               const float* __restrict__ b_g,
                               const float* __restrict__ w_b,
                               const float* __restrict__ b_b) {
    int p = blockIdx.x * blockDim.x + threadIdx.x;
    int b  = p >> 16;
    int hw = p & (HW_ - 1);
    int h  = hw >> 8;
    int w  = hw & (W_ - 1);
    float accg = b_g[0];
    float accb = b_b[0];
    #pragma unroll
    for (int kh = 0; kh < 3; kh++) {
        int hh = h + kh - 1;
        if (hh < 0 || hh >= H_) continue;
        #pragma unroll
        for (int kw = 0; kw < 3; kw++) {
            int ww = w + kw - 1;
            if (ww < 0 || ww >= W_) continue;
            float xv = g_xmap[(b << 16) | (hh << 8) | ww];
            accg += xv * w_g[kh * 3 + kw];
            accb += xv * w_b[kh * 3 + kw];
        }
    }
    float x = g_xmap[p];
    int m = (x > THRESH_) ? 1 : 0;
    g_mask[p] = (unsigned char)m;
    g_gmap[p] = accg;
    g_bmap[p] = accb;

    // block count reduction (integer -> deterministic)
    #pragma unroll
    for (int o = 16; o; o >>= 1) m += __shfl_xor_sync(0xFFFFFFFFu, m, o);
    __shared__ int sh[8];
    int warp = threadIdx.x >> 5, lane = threadIdx.x & 31;
    if (lane == 0) sh[warp] = m;
    __syncthreads();
    if (threadIdx.x == 0) {
        int t = 0;
        #pragma unroll
        for (int i = 0; i < 8; i++) t += sh[i];
        atomicAdd(&g_counts[b], t);
    }
}

// ============================================================
// Kernel 4: masked + total partial sums per (batch, chunk, channel)
// thread t -> channel (t&127), pixel parity (t>>7)
// ============================================================
__global__ void moments_kernel(const float* __restrict__ in) {
    int chunk = blockIdx.x;     // 0..NBLK_-1
    int b     = blockIdx.y;     // 0..B_-1
    int t     = threadIdx.x;    // 0..255
    int chan  = t & (C_ - 1);
    int par   = t >> 7;

    const float* base = in + ((size_t)b * HW_ + (size_t)chunk * PIX_PER_CHUNK_) * C_ + chan;
    const unsigned char* mbase = g_mask + b * HW_ + chunk * PIX_PER_CHUNK_;

    float s1v = 0.f, s2v = 0.f, s1 = 0.f, s2 = 0.f;
    #pragma unroll 8
    for (int i = par; i < PIX_PER_CHUNK_; i += 2) {
        float x  = __ldg(base + (size_t)i * C_);
        float fm = (float)mbase[i];
        s1  += x;
        s2  += x * x;
        s1v += x * fm;
        s2v += x * x * fm;
    }

    __shared__ float4 sh[256];
    sh[t] = make_float4(s1v, s2v, s1, s2);
    __syncthreads();
    if (t < C_) {
        float4 a = sh[t], c = sh[t + C_];
        a.x += c.x; a.y += c.y; a.z += c.z; a.w += c.w;
        g_partials[((size_t)b * NBLK_ + chunk) * C_ + t] = a;
    }
}

// ============================================================
// Kernel 5: reduce partials, compute mu / inv_std per (b, region, c)
// ============================================================
__global__ void finalize_kernel() {
    int id = blockIdx.x * blockDim.x + threadIdx.x;
    if (id >= B_ * C_) return;
    int b = id >> 7;
    int c = id & (C_ - 1);
    float s1v = 0.f, s2v = 0.f, s1 = 0.f, s2 = 0.f;
    for (int k = 0; k < NBLK_; k++) {
        float4 p = g_partials[((size_t)b * NBLK_ + k) * C_ + c];
        s1v += p.x; s2v += p.y; s1 += p.z; s2 += p.w;
    }
    float cnt_v = (float)g_counts[b];
    float cnt_m = (float)HW_ - cnt_v;
    float s1m = s1 - s1v;
    float s2m = s2 - s2v;

    // valid region (mask == 1)
    float fs_v  = cnt_v + EPS_;
    float mu_v  = s1v / fs_v;
    float var_v = (s2v - 2.f * mu_v * s1v + mu_v * mu_v * cnt_v) / fs_v;
    float is_v  = 1.0f / sqrtf(var_v + EPS_);
    // masked region (mask == 0)
    float fs_m  = cnt_m + EPS_;
    float mu_m  = s1m / fs_m;
    float var_m = (s2m - 2.f * mu_m * s1m + mu_m * mu_m * cnt_m) / fs_m;
    float is_m  = 1.0f / sqrtf(var_m + EPS_);

    // layout: [b][region][c][{mu, istd}], region 1 = valid
    float* pv = g_params + (((size_t)b * 2 + 1) * C_ + c) * 2;
    pv[0] = mu_v; pv[1] = is_v;
    float* pm = g_params + (((size_t)b * 2 + 0) * C_ + c) * 2;
    pm[0] = mu_m; pm[1] = is_m;
}

// ============================================================
// Kernel 6: out = (x - mu_r) * istd_r * beta + gamma
// float4 over channels; warp covers one pixel
// ============================================================
__global__ void apply_kernel(const float* __restrict__ in, float* __restrict__ out) {
    int i4 = blockIdx.x * blockDim.x + threadIdx.x;     // < P_ * 32
    int pixel = i4 >> 5;
    int c4    = i4 & 31;
    int b     = pixel >> 16;

    float4 v = ((const float4*)in)[i4];
    int   m     = g_mask[pixel];
    float beta  = g_bmap[pixel];
    float gamma = g_gmap[pixel];

    const float4* pp = (const float4*)(g_params + (((size_t)b * 2 + m) * C_ + c4 * 4) * 2);
    float4 p0 = pp[0];   // {mu0, is0, mu1, is1}
    float4 p1 = pp[1];   // {mu2, is2, mu3, is3}

    float4 o;
    o.x = (v.x - p0.x) * p0.y * beta + gamma;
    o.y = (v.y - p0.z) * p0.w * beta + gamma;
    o.z = (v.z - p1.x) * p1.y * beta + gamma;
    o.w = (v.w - p1.z) * p1.w * beta + gamma;
    ((float4*)out)[i4] = o;
}

// ============================================================
extern "C" void kernel_launch(void* const* d_in, const int* in_sizes, int n_in,
                              void* d_out, int out_size) {
    const float* in      = (const float*)d_in[0];
    const float* w_sr    = (const float*)d_in[1];
    const float* b_sr    = (const float*)d_in[2];
    const float* w_gamma = (const float*)d_in[3];
    const float* b_gamma = (const float*)d_in[4];
    const float* w_beta  = (const float*)d_in[5];
    const float* b_beta  = (const float*)d_in[6];
    float* out = (float*)d_out;

    // 1) channel pool: warp per pixel, 8 pixels per 256-thread block
    pool_kernel<<<P_ / 8, 256>>>(in);
    // 2) spatial-response conv + sigmoid
    conv_sr_kernel<<<P_ / 256, 256>>>(w_sr, b_sr);
    zero_counts_kernel<<<1, 32>>>();
    // 3) gamma/beta convs + mask + counts
    conv_gb_kernel<<<P_ / 256, 256>>>(w_gamma, b_gamma, w_beta, b_beta);
    // 4) moment partials
    moments_kernel<<<dim3(NBLK_, B_), 256>>>(in);
    // 5) finalize params
    finalize_kernel<<<(B_ * C_ + 255) / 256, 256>>>();
    // 6) normalize + affine
    apply_kernel<<<(P_ * 32) / 256, 256>>>(in, out);
}

// round 3
// speedup vs baseline: 1.1241x; 1.1241x over previous
#include <cuda_runtime.h>
#include <math.h>

#define B_ 8
#define H_ 256
#define W_ 256
#define C_ 128
#define HW_ (H_ * W_)          // 65536
#define P_ (B_ * HW_)          // 524288 pixels
#define NBLK_ 128              // reduction chunks per batch
#define PIX_PER_CHUNK_ (HW_ / NBLK_)   // 512
#define THRESH_ 0.8f
#define EPS_ 1e-3f

// ---- scratch (device globals; no allocation allowed) ----
__device__ float g_pooled[P_ * 2];                 // [pixel][2] = {max, avg}   4 MB
__device__ float g_gmap[P_];                       // gamma map                 2 MB
__device__ float g_bmap[P_];                       // beta map                  2 MB
__device__ unsigned char g_mask[P_];               // region mask               0.5 MB
__device__ int   g_counts[B_];                     // mask count per batch
__device__ float4 g_partials[B_ * NBLK_ * C_];     // {s1v,s2v,s1,s2}           2 MB
__device__ float g_params[B_ * 2 * C_ * 2];        // [b][region][c][{mu,istd}] 8 KB

// ============================================================
// Kernel 1: channel max/avg pool. 4 pixels per warp, batched loads (MLP=4).
// Also zeros the per-batch mask counts (block 0).
// ============================================================
__global__ void pool_kernel(const float* __restrict__ in) {
    if (blockIdx.x == 0 && threadIdx.x < B_) g_counts[threadIdx.x] = 0;

    int warp = threadIdx.x >> 5, lane = threadIdx.x & 31;
    int pix0 = blockIdx.x * 32 + warp * 4;
    const float4* p = (const float4*)in;

    float4 v[4];
    #pragma unroll
    for (int k = 0; k < 4; k++)
        v[k] = p[(size_t)(pix0 + k) * 32 + lane];

    float mx[4], sm[4];
    #pragma unroll
    for (int k = 0; k < 4; k++) {
        mx[k] = fmaxf(fmaxf(v[k].x, v[k].y), fmaxf(v[k].z, v[k].w));
        sm[k] = (v[k].x + v[k].y) + (v[k].z + v[k].w);
    }
    #pragma unroll
    for (int o = 16; o; o >>= 1) {
        #pragma unroll
        for (int k = 0; k < 4; k++) {
            mx[k] = fmaxf(mx[k], __shfl_xor_sync(0xFFFFFFFFu, mx[k], o));
            sm[k] += __shfl_xor_sync(0xFFFFFFFFu, sm[k], o);
        }
    }
    if (lane == 0) {
        float2* po = ((float2*)g_pooled) + pix0;
        #pragma unroll
        for (int k = 0; k < 4; k++) {
            float2 r; r.x = mx[k]; r.y = sm[k] * (1.0f / (float)C_);
            po[k] = r;
        }
    }
}

// ============================================================
// Kernel 2: FUSED conv pipeline. Per 32x32 tile:
//   load pooled (36x36 halo, zero-padded) -> shared
//   compute xmap = sigmoid(conv_sr) on 34x34 (zero outside image) -> shared
//   compute gamma/beta 3x3 convs, mask, per-batch count on 32x32 interior
// xmap never touches HBM.
// ============================================================
__global__ void fused_conv_kernel(const float* __restrict__ w_sr,
                                  const float* __restrict__ b_sr,
                                  const float* __restrict__ w_g,
                                  const float* __restrict__ b_g,
                                  const float* __restrict__ w_b,
                                  const float* __restrict__ b_b) {
    __shared__ float2 sp[36][37];
    __shared__ float  xm[34][35];
    __shared__ float  swsr[18], swg[9], swb[9], sbias[3];
    __shared__ int    scnt[8];

    int t = threadIdx.x;
    int b  = blockIdx.x >> 6;
    int tt = blockIdx.x & 63;
    int th = (tt >> 3) << 5;
    int tw = (tt & 7) << 5;
    int bbase = b << 16;

    if (t < 18) swsr[t] = w_sr[t];
    if (t < 9) { swg[t] = w_g[t]; swb[t] = w_b[t]; }
    if (t == 0) { sbias[0] = b_sr[0]; sbias[1] = b_g[0]; sbias[2] = b_b[0]; }

    // load pooled halo 36x36
    const float2* pooled2 = (const float2*)g_pooled;
    for (int l = t; l < 36 * 36; l += 256) {
        int i = l / 36, j = l % 36;
        int h = th - 2 + i, w = tw - 2 + j;
        float2 val = make_float2(0.f, 0.f);
        if (h >= 0 && h < H_ && w >= 0 && w < W_)
            val = pooled2[bbase + (h << 8) + w];
        sp[i][j] = val;
    }
    __syncthreads();

    // xmap on 34x34 (positions th-1..th+32)
    for (int l = t; l < 34 * 34; l += 256) {
        int i = l / 34, j = l % 34;
        int h = th - 1 + i, w = tw - 1 + j;
        float x = 0.f;
        if (h >= 0 && h < H_ && w >= 0 && w < W_) {
            float acc = sbias[0];
            #pragma unroll
            for (int kh = 0; kh < 3; kh++)
                #pragma unroll
                for (int kw = 0; kw < 3; kw++) {
                    float2 pv = sp[i + kh][j + kw];
                    acc += pv.x * swsr[(kh * 3 + kw) * 2]
                         + pv.y * swsr[(kh * 3 + kw) * 2 + 1];
                }
            x = 1.0f / (1.0f + expf(-acc));
        }
        xm[i][j] = x;
    }
    __syncthreads();

    // interior 32x32: gamma/beta convs + mask + count
    int cnt = 0;
    #pragma unroll
    for (int it = 0; it < 4; it++) {
        int l = t + it * 256;
        int i = l >> 5, j = l & 31;
        float accg = sbias[1], accb = sbias[2];
        #pragma unroll
        for (int kh = 0; kh < 3; kh++)
            #pragma unroll
            for (int kw = 0; kw < 3; kw++) {
                float xv = xm[i + kh][j + kw];
                accg += xv * swg[kh * 3 + kw];
                accb += xv * swb[kh * 3 + kw];
            }
        float x = xm[i + 1][j + 1];
        int m = (x > THRESH_) ? 1 : 0;
        int pixel = bbase + ((th + i) << 8) + tw + j;
        g_mask[pixel] = (unsigned char)m;
        g_gmap[pixel] = accg;
        g_bmap[pixel] = accb;
        cnt += m;
    }
    #pragma unroll
    for (int o = 16; o; o >>= 1) cnt += __shfl_xor_sync(0xFFFFFFFFu, cnt, o);
    int warp = t >> 5, lane = t & 31;
    if (lane == 0) scnt[warp] = cnt;
    __syncthreads();
    if (t == 0) {
        int s = 0;
        #pragma unroll
        for (int i = 0; i < 8; i++) s += scnt[i];
        atomicAdd(&g_counts[b], s);
    }
}

// ============================================================
// Kernel 3: masked + total partial sums per (batch, chunk, channel).
// float4 loads (4 channels/thread), unrolled x4 for MLP.
// ============================================================
__global__ void moments_kernel(const float* __restrict__ in) {
    int chunk = blockIdx.x;     // 0..NBLK_-1
    int b     = blockIdx.y;     // 0..B_-1
    int t     = threadIdx.x;    // 0..255
    int c4    = t & 31;         // float4 channel group
    int sub   = t >> 5;         // 0..7

    __shared__ float smask[PIX_PER_CHUNK_];
    if (t < 128) {
        uchar4 m4 = ((const uchar4*)(g_mask + b * HW_ + chunk * PIX_PER_CHUNK_))[t];
        smask[t * 4 + 0] = (float)m4.x;
        smask[t * 4 + 1] = (float)m4.y;
        smask[t * 4 + 2] = (float)m4.z;
        smask[t * 4 + 3] = (float)m4.w;
    }
    __syncthreads();

    const float4* base = (const float4*)(in + ((size_t)b * HW_ + (size_t)chunk * PIX_PER_CHUNK_) * C_) + c4;

    float4 s1  = make_float4(0,0,0,0), s2  = make_float4(0,0,0,0);
    float4 s1v = make_float4(0,0,0,0), s2v = make_float4(0,0,0,0);

    for (int i0 = sub; i0 < PIX_PER_CHUNK_; i0 += 32) {
        float4 v[4];
        #pragma unroll
        for (int k = 0; k < 4; k++)
            v[k] = base[(size_t)(i0 + 8 * k) * 32];
        #pragma unroll
        for (int k = 0; k < 4; k++) {
            float fm = smask[i0 + 8 * k];
            s1.x += v[k].x;              s1.y += v[k].y;
            s1.z += v[k].z;              s1.w += v[k].w;
            s2.x += v[k].x * v[k].x;     s2.y += v[k].y * v[k].y;
            s2.z += v[k].z * v[k].z;     s2.w += v[k].w * v[k].w;
            s1v.x += v[k].x * fm;        s1v.y += v[k].y * fm;
            s1v.z += v[k].z * fm;        s1v.w += v[k].w * fm;
            s2v.x += v[k].x * v[k].x * fm; s2v.y += v[k].y * v[k].y * fm;
            s2v.z += v[k].z * v[k].z * fm; s2v.w += v[k].w * v[k].w * fm;
        }
    }

    __shared__ float4 r1[256], r2[256], r3[256], r4[256];
    r1[t] = s1v; r2[t] = s2v; r3[t] = s1; r4[t] = s2;
    __syncthreads();

    if (t < C_) {
        int cc4 = t >> 2, k = t & 3;
        float a1 = 0.f, a2 = 0.f, a3 = 0.f, a4 = 0.f;
        #pragma unroll
        for (int s = 0; s < 8; s++) {
            int idx = s * 32 + cc4;
            a1 += ((const float*)&r1[idx])[k];
            a2 += ((const float*)&r2[idx])[k];
            a3 += ((const float*)&r3[idx])[k];
            a4 += ((const float*)&r4[idx])[k];
        }
        g_partials[((size_t)b * NBLK_ + chunk) * C_ + t] = make_float4(a1, a2, a3, a4);
    }
}

// ============================================================
// Kernel 4: reduce partials, compute mu / inv_std per (b, region, c)
// ============================================================
__global__ void finalize_kernel() {
    int id = blockIdx.x * blockDim.x + threadIdx.x;
    if (id >= B_ * C_) return;
    int b = id >> 7;
    int c = id & (C_ - 1);
    float s1v = 0.f, s2v = 0.f, s1 = 0.f, s2 = 0.f;
    for (int k = 0; k < NBLK_; k++) {
        float4 p = g_partials[((size_t)b * NBLK_ + k) * C_ + c];
        s1v += p.x; s2v += p.y; s1 += p.z; s2 += p.w;
    }
    float cnt_v = (float)g_counts[b];
    float cnt_m = (float)HW_ - cnt_v;
    float s1m = s1 - s1v;
    float s2m = s2 - s2v;

    float fs_v  = cnt_v + EPS_;
    float mu_v  = s1v / fs_v;
    float var_v = (s2v - 2.f * mu_v * s1v + mu_v * mu_v * cnt_v) / fs_v;
    float is_v  = 1.0f / sqrtf(var_v + EPS_);
    float fs_m  = cnt_m + EPS_;
    float mu_m  = s1m / fs_m;
    float var_m = (s2m - 2.f * mu_m * s1m + mu_m * mu_m * cnt_m) / fs_m;
    float is_m  = 1.0f / sqrtf(var_m + EPS_);

    float* pv = g_params + (((size_t)b * 2 + 1) * C_ + c) * 2;
    pv[0] = mu_v; pv[1] = is_v;
    float* pm = g_params + (((size_t)b * 2 + 0) * C_ + c) * 2;
    pm[0] = mu_m; pm[1] = is_m;
}

// ============================================================
// Kernel 5: out = (x - mu_r) * istd_r * beta + gamma
// ILP=4 (4 float4 loads in flight), params cached in shared.
// Block covers 32 pixels (1024 float4s), all within one batch.
// ============================================================
__global__ void apply_kernel(const float* __restrict__ in, float* __restrict__ out) {
    int t = threadIdx.x;
    size_t base = (size_t)blockIdx.x * 1024;
    int pix0 = blockIdx.x * 32;
    int b = pix0 >> 16;

    __shared__ float4 sparams[128];   // [region(2)][c4(32)][2]
    if (t < 128) sparams[t] = ((const float4*)g_params)[b * 128 + t];
    __syncthreads();

    const float4* in4 = (const float4*)in;
    float4* out4 = (float4*)out;

    float4 v[4];
    #pragma unroll
    for (int k = 0; k < 4; k++)
        v[k] = in4[base + t + 256 * k];

    #pragma unroll
    for (int k = 0; k < 4; k++) {
        int i4  = t + 256 * k;
        int pix = pix0 + (i4 >> 5);
        int c4  = i4 & 31;
        int m        = g_mask[pix];
        float beta   = g_bmap[pix];
        float gamma  = g_gmap[pix];
        float4 p0 = sparams[m * 64 + c4 * 2];      // {mu0,is0,mu1,is1}
        float4 p1 = sparams[m * 64 + c4 * 2 + 1];  // {mu2,is2,mu3,is3}
        float4 o;
        o.x = (v[k].x - p0.x) * p0.y * beta + gamma;
        o.y = (v[k].y - p0.z) * p0.w * beta + gamma;
        o.z = (v[k].z - p1.x) * p1.y * beta + gamma;
        o.w = (v[k].w - p1.z) * p1.w * beta + gamma;
        out4[base + i4] = o;
    }
}

// ============================================================
extern "C" void kernel_launch(void* const* d_in, const int* in_sizes, int n_in,
                              void* d_out, int out_size) {
    const float* in      = (const float*)d_in[0];
    const float* w_sr    = (const float*)d_in[1];
    const float* b_sr    = (const float*)d_in[2];
    const float* w_gamma = (const float*)d_in[3];
    const float* b_gamma = (const float*)d_in[4];
    const float* w_beta  = (const float*)d_in[5];
    const float* b_beta  = (const float*)d_in[6];
    float* out = (float*)d_out;

    pool_kernel<<<P_ / 32, 256>>>(in);
    fused_conv_kernel<<<B_ * 64, 256>>>(w_sr, b_sr, w_gamma, b_gamma, w_beta, b_beta);
    moments_kernel<<<dim3(NBLK_, B_), 256>>>(in);
    finalize_kernel<<<(B_ * C_ + 255) / 256, 256>>>();
    apply_kernel<<<P_ / 32, 256>>>(in, out);
}

// round 4
// speedup vs baseline: 1.1714x; 1.0421x over previous
#include <cuda_runtime.h>
#include <math.h>

#define B_ 8
#define H_ 256
#define W_ 256
#define C_ 128
#define HW_ (H_ * W_)          // 65536
#define P_ (B_ * HW_)          // 524288 pixels
#define NBLK_ 128              // reduction chunks per batch
#define PIX_PER_CHUNK_ (HW_ / NBLK_)   // 512
#define THRESH_ 0.8f
#define EPS_ 1e-3f

// ---- scratch (device globals; no allocation allowed) ----
__device__ float g_pooled[P_ * 2];                 // [pixel][2] = {max, avg}   4 MB
__device__ float g_gmap[P_];                       // gamma map                 2 MB
__device__ float g_bmap[P_];                       // beta map                  2 MB
__device__ unsigned char g_mask[P_];               // region mask               0.5 MB
__device__ int   g_counts[B_];                     // mask count per batch
__device__ float4 g_partials[B_ * NBLK_ * C_];     // {s1v,s2v,s1,s2}           2 MB
__device__ float g_params[B_ * 2 * C_ * 2];        // [b][region][c][{mu,istd}] 8 KB

// ============================================================
// Kernel 1: channel max/avg pool. 4 pixels per warp, batched loads (MLP=4).
// Also zeros the per-batch mask counts (block 0).
// ============================================================
__global__ void pool_kernel(const float* __restrict__ in) {
    if (blockIdx.x == 0 && threadIdx.x < B_) g_counts[threadIdx.x] = 0;

    int warp = threadIdx.x >> 5, lane = threadIdx.x & 31;
    int pix0 = blockIdx.x * 32 + warp * 4;
    const float4* p = (const float4*)in;

    float4 v[4];
    #pragma unroll
    for (int k = 0; k < 4; k++)
        v[k] = p[(size_t)(pix0 + k) * 32 + lane];

    float mx[4], sm[4];
    #pragma unroll
    for (int k = 0; k < 4; k++) {
        mx[k] = fmaxf(fmaxf(v[k].x, v[k].y), fmaxf(v[k].z, v[k].w));
        sm[k] = (v[k].x + v[k].y) + (v[k].z + v[k].w);
    }
    #pragma unroll
    for (int o = 16; o; o >>= 1) {
        #pragma unroll
        for (int k = 0; k < 4; k++) {
            mx[k] = fmaxf(mx[k], __shfl_xor_sync(0xFFFFFFFFu, mx[k], o));
            sm[k] += __shfl_xor_sync(0xFFFFFFFFu, sm[k], o);
        }
    }
    if (lane == 0) {
        float2* po = ((float2*)g_pooled) + pix0;
        #pragma unroll
        for (int k = 0; k < 4; k++) {
            float2 r; r.x = mx[k]; r.y = sm[k] * (1.0f / (float)C_);
            po[k] = r;
        }
    }
}

// ============================================================
// Kernel 2: FUSED conv pipeline (32x32 tiles, xmap stays in shared).
// ============================================================
__global__ void fused_conv_kernel(const float* __restrict__ w_sr,
                                  const float* __restrict__ b_sr,
                                  const float* __restrict__ w_g,
                                  const float* __restrict__ b_g,
                                  const float* __restrict__ w_b,
                                  const float* __restrict__ b_b) {
    __shared__ float2 sp[36][37];
    __shared__ float  xm[34][35];
    __shared__ float  swsr[18], swg[9], swb[9], sbias[3];
    __shared__ int    scnt[8];

    int t = threadIdx.x;
    int b  = blockIdx.x >> 6;
    int tt = blockIdx.x & 63;
    int th = (tt >> 3) << 5;
    int tw = (tt & 7) << 5;
    int bbase = b << 16;

    if (t < 18) swsr[t] = w_sr[t];
    if (t < 9) { swg[t] = w_g[t]; swb[t] = w_b[t]; }
    if (t == 0) { sbias[0] = b_sr[0]; sbias[1] = b_g[0]; sbias[2] = b_b[0]; }

    const float2* pooled2 = (const float2*)g_pooled;
    for (int l = t; l < 36 * 36; l += 256) {
        int i = l / 36, j = l % 36;
        int h = th - 2 + i, w = tw - 2 + j;
        float2 val = make_float2(0.f, 0.f);
        if (h >= 0 && h < H_ && w >= 0 && w < W_)
            val = pooled2[bbase + (h << 8) + w];
        sp[i][j] = val;
    }
    __syncthreads();

    for (int l = t; l < 34 * 34; l += 256) {
        int i = l / 34, j = l % 34;
        int h = th - 1 + i, w = tw - 1 + j;
        float x = 0.f;
        if (h >= 0 && h < H_ && w >= 0 && w < W_) {
            float acc = sbias[0];
            #pragma unroll
            for (int kh = 0; kh < 3; kh++)
                #pragma unroll
                for (int kw = 0; kw < 3; kw++) {
                    float2 pv = sp[i + kh][j + kw];
                    acc += pv.x * swsr[(kh * 3 + kw) * 2]
                         + pv.y * swsr[(kh * 3 + kw) * 2 + 1];
                }
            x = 1.0f / (1.0f + expf(-acc));
        }
        xm[i][j] = x;
    }
    __syncthreads();

    int cnt = 0;
    #pragma unroll
    for (int it = 0; it < 4; it++) {
        int l = t + it * 256;
        int i = l >> 5, j = l & 31;
        float accg = sbias[1], accb = sbias[2];
        #pragma unroll
        for (int kh = 0; kh < 3; kh++)
            #pragma unroll
            for (int kw = 0; kw < 3; kw++) {
                float xv = xm[i + kh][j + kw];
                accg += xv * swg[kh * 3 + kw];
                accb += xv * swb[kh * 3 + kw];
            }
        float x = xm[i + 1][j + 1];
        int m = (x > THRESH_) ? 1 : 0;
        int pixel = bbase + ((th + i) << 8) + tw + j;
        g_mask[pixel] = (unsigned char)m;
        g_gmap[pixel] = accg;
        g_bmap[pixel] = accb;
        cnt += m;
    }
    #pragma unroll
    for (int o = 16; o; o >>= 1) cnt += __shfl_xor_sync(0xFFFFFFFFu, cnt, o);
    int warp = t >> 5, lane = t & 31;
    if (lane == 0) scnt[warp] = cnt;
    __syncthreads();
    if (t == 0) {
        int s = 0;
        #pragma unroll
        for (int i = 0; i < 8; i++) s += scnt[i];
        atomicAdd(&g_counts[b], s);
    }
}

// ============================================================
// Kernel 3: masked + total partial sums per (batch, chunk, channel).
// ============================================================
__global__ void moments_kernel(const float* __restrict__ in) {
    int chunk = blockIdx.x;
    int b     = blockIdx.y;
    int t     = threadIdx.x;
    int c4    = t & 31;
    int sub   = t >> 5;

    __shared__ float smask[PIX_PER_CHUNK_];
    if (t < 128) {
        uchar4 m4 = ((const uchar4*)(g_mask + b * HW_ + chunk * PIX_PER_CHUNK_))[t];
        smask[t * 4 + 0] = (float)m4.x;
        smask[t * 4 + 1] = (float)m4.y;
        smask[t * 4 + 2] = (float)m4.z;
        smask[t * 4 + 3] = (float)m4.w;
    }
    __syncthreads();

    const float4* base = (const float4*)(in + ((size_t)b * HW_ + (size_t)chunk * PIX_PER_CHUNK_) * C_) + c4;

    float4 s1  = make_float4(0,0,0,0), s2  = make_float4(0,0,0,0);
    float4 s1v = make_float4(0,0,0,0), s2v = make_float4(0,0,0,0);

    for (int i0 = sub; i0 < PIX_PER_CHUNK_; i0 += 32) {
        float4 v[4];
        #pragma unroll
        for (int k = 0; k < 4; k++)
            v[k] = base[(size_t)(i0 + 8 * k) * 32];
        #pragma unroll
        for (int k = 0; k < 4; k++) {
            float fm = smask[i0 + 8 * k];
            s1.x += v[k].x;              s1.y += v[k].y;
            s1.z += v[k].z;              s1.w += v[k].w;
            s2.x += v[k].x * v[k].x;     s2.y += v[k].y * v[k].y;
            s2.z += v[k].z * v[k].z;     s2.w += v[k].w * v[k].w;
            s1v.x += v[k].x * fm;        s1v.y += v[k].y * fm;
            s1v.z += v[k].z * fm;        s1v.w += v[k].w * fm;
            s2v.x += v[k].x * v[k].x * fm; s2v.y += v[k].y * v[k].y * fm;
            s2v.z += v[k].z * v[k].z * fm; s2v.w += v[k].w * v[k].w * fm;
        }
    }

    __shared__ float4 r1[256], r2[256], r3[256], r4[256];
    r1[t] = s1v; r2[t] = s2v; r3[t] = s1; r4[t] = s2;
    __syncthreads();

    if (t < C_) {
        int cc4 = t >> 2, k = t & 3;
        float a1 = 0.f, a2 = 0.f, a3 = 0.f, a4 = 0.f;
        #pragma unroll
        for (int s = 0; s < 8; s++) {
            int idx = s * 32 + cc4;
            a1 += ((const float*)&r1[idx])[k];
            a2 += ((const float*)&r2[idx])[k];
            a3 += ((const float*)&r3[idx])[k];
            a4 += ((const float*)&r4[idx])[k];
        }
        g_partials[((size_t)b * NBLK_ + chunk) * C_ + t] = make_float4(a1, a2, a3, a4);
    }
}

// ============================================================
// Kernel 4: reduce partials -> mu / inv_std. ONE WARP per (b,c):
// lane l sums partials[l], [l+32], [l+64], [l+96] (MLP=4), then
// warp-shuffle reduce; lane 0 writes both regions' params.
// 1024 warps total = 128 blocks x 256 threads.
// ============================================================
__global__ void finalize_kernel() {
    int gwarp = (blockIdx.x * blockDim.x + threadIdx.x) >> 5;  // 0..1023 = (b,c)
    int lane  = threadIdx.x & 31;
    int b = gwarp >> 7;
    int c = gwarp & (C_ - 1);

    const float4* pp = g_partials + (size_t)b * NBLK_ * C_ + c;
    float4 a[4];
    #pragma unroll
    for (int k = 0; k < 4; k++)
        a[k] = pp[(size_t)(lane + 32 * k) * C_];

    float s1v = a[0].x + a[1].x + a[2].x + a[3].x;
    float s2v = a[0].y + a[1].y + a[2].y + a[3].y;
    float s1  = a[0].z + a[1].z + a[2].z + a[3].z;
    float s2  = a[0].w + a[1].w + a[2].w + a[3].w;

    #pragma unroll
    for (int o = 16; o; o >>= 1) {
        s1v += __shfl_xor_sync(0xFFFFFFFFu, s1v, o);
        s2v += __shfl_xor_sync(0xFFFFFFFFu, s2v, o);
        s1  += __shfl_xor_sync(0xFFFFFFFFu, s1, o);
        s2  += __shfl_xor_sync(0xFFFFFFFFu, s2, o);
    }

    if (lane == 0) {
        float cnt_v = (float)g_counts[b];
        float cnt_m = (float)HW_ - cnt_v;
        float s1m = s1 - s1v;
        float s2m = s2 - s2v;

        float fs_v  = cnt_v + EPS_;
        float mu_v  = s1v / fs_v;
        float var_v = (s2v - 2.f * mu_v * s1v + mu_v * mu_v * cnt_v) / fs_v;
        float is_v  = 1.0f / sqrtf(var_v + EPS_);
        float fs_m  = cnt_m + EPS_;
        float mu_m  = s1m / fs_m;
        float var_m = (s2m - 2.f * mu_m * s1m + mu_m * mu_m * cnt_m) / fs_m;
        float is_m  = 1.0f / sqrtf(var_m + EPS_);

        ((float2*)g_params)[((size_t)b * 2 + 1) * C_ + c] = make_float2(mu_v, is_v);
        ((float2*)g_params)[((size_t)b * 2 + 0) * C_ + c] = make_float2(mu_m, is_m);
    }
}

// ============================================================
// Kernel 5: out = (x - mu_r) * istd_r * beta + gamma
// ============================================================
__global__ void apply_kernel(const float* __restrict__ in, float* __restrict__ out) {
    int t = threadIdx.x;
    size_t base = (size_t)blockIdx.x * 1024;
    int pix0 = blockIdx.x * 32;
    int b = pix0 >> 16;

    __shared__ float4 sparams[128];   // [region(2)][c4(32)][2]
    if (t < 128) sparams[t] = ((const float4*)g_params)[b * 128 + t];
    __syncthreads();

    const float4* in4 = (const float4*)in;
    float4* out4 = (float4*)out;

    float4 v[4];
    #pragma unroll
    for (int k = 0; k < 4; k++)
        v[k] = in4[base + t + 256 * k];

    #pragma unroll
    for (int k = 0; k < 4; k++) {
        int i4  = t + 256 * k;
        int pix = pix0 + (i4 >> 5);
        int c4  = i4 & 31;
        int m        = g_mask[pix];
        float beta   = g_bmap[pix];
        float gamma  = g_gmap[pix];
        float4 p0 = sparams[m * 64 + c4 * 2];
        float4 p1 = sparams[m * 64 + c4 * 2 + 1];
        float4 o;
        o.x = (v[k].x - p0.x) * p0.y * beta + gamma;
        o.y = (v[k].y - p0.z) * p0.w * beta + gamma;
        o.z = (v[k].z - p1.x) * p1.y * beta + gamma;
        o.w = (v[k].w - p1.z) * p1.w * beta + gamma;
        out4[base + i4] = o;
    }
}

// ============================================================
extern "C" void kernel_launch(void* const* d_in, const int* in_sizes, int n_in,
                              void* d_out, int out_size) {
    const float* in      = (const float*)d_in[0];
    const float* w_sr    = (const float*)d_in[1];
    const float* b_sr    = (const float*)d_in[2];
    const float* w_gamma = (const float*)d_in[3];
    const float* b_gamma = (const float*)d_in[4];
    const float* w_beta  = (const float*)d_in[5];
    const float* b_beta  = (const float*)d_in[6];
    float* out = (float*)d_out;

    pool_kernel<<<P_ / 32, 256>>>(in);
    fused_conv_kernel<<<B_ * 64, 256>>>(w_sr, b_sr, w_gamma, b_gamma, w_beta, b_beta);
    moments_kernel<<<dim3(NBLK_, B_), 256>>>(in);
    finalize_kernel<<<(B_ * C_) / 8, 256>>>();
    apply_kernel<<<P_ / 32, 256>>>(in, out);
}

// round 5
// speedup vs baseline: 1.1841x; 1.0108x over previous
#include <cuda_runtime.h>
#include <math.h>

#define B_ 8
#define H_ 256
#define W_ 256
#define C_ 128
#define HW_ (H_ * W_)          // 65536
#define P_ (B_ * HW_)          // 524288 pixels
#define NBLK_ 128              // reduction chunks per batch
#define PIX_PER_CHUNK_ (HW_ / NBLK_)   // 512
#define THRESH_ 0.8f
#define EPS_ 1e-3f

// ---- scratch (device globals; no allocation allowed) ----
__device__ float g_pooled[P_ * 2];                 // [pixel][2] = {max, avg}   4 MB
__device__ float g_gmap[P_];                       // gamma map                 2 MB
__device__ float g_bmap[P_];                       // beta map                  2 MB
__device__ unsigned char g_mask[P_];               // region mask               0.5 MB
__device__ int   g_counts[B_];                     // mask count per batch
__device__ int   g_done[B_];                       // moments completion counter
__device__ float4 g_partials[B_ * NBLK_ * C_];     // {s1v,s2v,s1,s2}           2 MB
__device__ float g_params[B_ * 2 * C_ * 2];        // [b][region][c][{mu,istd}] 8 KB

// ============================================================
// Kernel 1: channel max/avg pool. 4 pixels per warp, batched loads (MLP=4).
// Block 0 also zeros the per-batch counters.
// ============================================================
__global__ void pool_kernel(const float* __restrict__ in) {
    if (blockIdx.x == 0 && threadIdx.x < B_) {
        g_counts[threadIdx.x] = 0;
        g_done[threadIdx.x] = 0;
    }

    int warp = threadIdx.x >> 5, lane = threadIdx.x & 31;
    int pix0 = blockIdx.x * 32 + warp * 4;
    const float4* p = (const float4*)in;

    float4 v[4];
    #pragma unroll
    for (int k = 0; k < 4; k++)
        v[k] = p[(size_t)(pix0 + k) * 32 + lane];

    float mx[4], sm[4];
    #pragma unroll
    for (int k = 0; k < 4; k++) {
        mx[k] = fmaxf(fmaxf(v[k].x, v[k].y), fmaxf(v[k].z, v[k].w));
        sm[k] = (v[k].x + v[k].y) + (v[k].z + v[k].w);
    }
    #pragma unroll
    for (int o = 16; o; o >>= 1) {
        #pragma unroll
        for (int k = 0; k < 4; k++) {
            mx[k] = fmaxf(mx[k], __shfl_xor_sync(0xFFFFFFFFu, mx[k], o));
            sm[k] += __shfl_xor_sync(0xFFFFFFFFu, sm[k], o);
        }
    }
    if (lane == 0) {
        float2* po = ((float2*)g_pooled) + pix0;
        #pragma unroll
        for (int k = 0; k < 4; k++) {
            float2 r; r.x = mx[k]; r.y = sm[k] * (1.0f / (float)C_);
            po[k] = r;
        }
    }
}

// ============================================================
// Kernel 2: FUSED conv pipeline (32x32 tiles, xmap stays in shared).
// ============================================================
__global__ void fused_conv_kernel(const float* __restrict__ w_sr,
                                  const float* __restrict__ b_sr,
                                  const float* __restrict__ w_g,
                                  const float* __restrict__ b_g,
                                  const float* __restrict__ w_b,
                                  const float* __restrict__ b_b) {
    __shared__ float2 sp[36][37];
    __shared__ float  xm[34][35];
    __shared__ float  swsr[18], swg[9], swb[9], sbias[3];
    __shared__ int    scnt[8];

    int t = threadIdx.x;
    int b  = blockIdx.x >> 6;
    int tt = blockIdx.x & 63;
    int th = (tt >> 3) << 5;
    int tw = (tt & 7) << 5;
    int bbase = b << 16;

    if (t < 18) swsr[t] = w_sr[t];
    if (t < 9) { swg[t] = w_g[t]; swb[t] = w_b[t]; }
    if (t == 0) { sbias[0] = b_sr[0]; sbias[1] = b_g[0]; sbias[2] = b_b[0]; }

    const float2* pooled2 = (const float2*)g_pooled;
    for (int l = t; l < 36 * 36; l += 256) {
        int i = l / 36, j = l % 36;
        int h = th - 2 + i, w = tw - 2 + j;
        float2 val = make_float2(0.f, 0.f);
        if (h >= 0 && h < H_ && w >= 0 && w < W_)
            val = pooled2[bbase + (h << 8) + w];
        sp[i][j] = val;
    }
    __syncthreads();

    for (int l = t; l < 34 * 34; l += 256) {
        int i = l / 34, j = l % 34;
        int h = th - 1 + i, w = tw - 1 + j;
        float x = 0.f;
        if (h >= 0 && h < H_ && w >= 0 && w < W_) {
            float acc = sbias[0];
            #pragma unroll
            for (int kh = 0; kh < 3; kh++)
                #pragma unroll
                for (int kw = 0; kw < 3; kw++) {
                    float2 pv = sp[i + kh][j + kw];
                    acc += pv.x * swsr[(kh * 3 + kw) * 2]
                         + pv.y * swsr[(kh * 3 + kw) * 2 + 1];
                }
            x = 1.0f / (1.0f + expf(-acc));
        }
        xm[i][j] = x;
    }
    __syncthreads();

    int cnt = 0;
    #pragma unroll
    for (int it = 0; it < 4; it++) {
        int l = t + it * 256;
        int i = l >> 5, j = l & 31;
        float accg = sbias[1], accb = sbias[2];
        #pragma unroll
        for (int kh = 0; kh < 3; kh++)
            #pragma unroll
            for (int kw = 0; kw < 3; kw++) {
                float xv = xm[i + kh][j + kw];
                accg += xv * swg[kh * 3 + kw];
                accb += xv * swb[kh * 3 + kw];
            }
        float x = xm[i + 1][j + 1];
        int m = (x > THRESH_) ? 1 : 0;
        int pixel = bbase + ((th + i) << 8) + tw + j;
        g_mask[pixel] = (unsigned char)m;
        g_gmap[pixel] = accg;
        g_bmap[pixel] = accb;
        cnt += m;
    }
    #pragma unroll
    for (int o = 16; o; o >>= 1) cnt += __shfl_xor_sync(0xFFFFFFFFu, cnt, o);
    int warp = t >> 5, lane = t & 31;
    if (lane == 0) scnt[warp] = cnt;
    __syncthreads();
    if (t == 0) {
        int s = 0;
        #pragma unroll
        for (int i = 0; i < 8; i++) s += scnt[i];
        atomicAdd(&g_counts[b], s);
    }
}

// ============================================================
// Kernel 3: masked + total partial sums per (batch, chunk, channel),
// batches processed in REVERSE order (L2 reuse from pool's tail).
// The LAST block of each batch also finalizes mu/invstd for that batch
// (partials are L2-hot; deterministic fixed-order reduction).
// ============================================================
__global__ void moments_kernel(const float* __restrict__ in) {
    int chunk = blockIdx.x;
    int b     = (B_ - 1) - blockIdx.y;   // reverse batch order
    int t     = threadIdx.x;
    int c4    = t & 31;
    int sub   = t >> 5;

    __shared__ float smask[PIX_PER_CHUNK_];
    if (t < 128) {
        uchar4 m4 = ((const uchar4*)(g_mask + b * HW_ + chunk * PIX_PER_CHUNK_))[t];
        smask[t * 4 + 0] = (float)m4.x;
        smask[t * 4 + 1] = (float)m4.y;
        smask[t * 4 + 2] = (float)m4.z;
        smask[t * 4 + 3] = (float)m4.w;
    }
    __syncthreads();

    const float4* base = (const float4*)(in + ((size_t)b * HW_ + (size_t)chunk * PIX_PER_CHUNK_) * C_) + c4;

    float4 s1  = make_float4(0,0,0,0), s2  = make_float4(0,0,0,0);
    float4 s1v = make_float4(0,0,0,0), s2v = make_float4(0,0,0,0);

    for (int i0 = sub; i0 < PIX_PER_CHUNK_; i0 += 32) {
        float4 v[4];
        #pragma unroll
        for (int k = 0; k < 4; k++)
            v[k] = base[(size_t)(i0 + 8 * k) * 32];
        #pragma unroll
        for (int k = 0; k < 4; k++) {
            float fm = smask[i0 + 8 * k];
            s1.x += v[k].x;              s1.y += v[k].y;
            s1.z += v[k].z;              s1.w += v[k].w;
            s2.x += v[k].x * v[k].x;     s2.y += v[k].y * v[k].y;
            s2.z += v[k].z * v[k].z;     s2.w += v[k].w * v[k].w;
            s1v.x += v[k].x * fm;        s1v.y += v[k].y * fm;
            s1v.z += v[k].z * fm;        s1v.w += v[k].w * fm;
            s2v.x += v[k].x * v[k].x * fm; s2v.y += v[k].y * v[k].y * fm;
            s2v.z += v[k].z * v[k].z * fm; s2v.w += v[k].w * v[k].w * fm;
        }
    }

    __shared__ float4 r1[256], r2[256], r3[256], r4[256];
    r1[t] = s1v; r2[t] = s2v; r3[t] = s1; r4[t] = s2;
    __syncthreads();

    if (t < C_) {
        int cc4 = t >> 2, k = t & 3;
        float a1 = 0.f, a2 = 0.f, a3 = 0.f, a4 = 0.f;
        #pragma unroll
        for (int s = 0; s < 8; s++) {
            int idx = s * 32 + cc4;
            a1 += ((const float*)&r1[idx])[k];
            a2 += ((const float*)&r2[idx])[k];
            a3 += ((const float*)&r3[idx])[k];
            a4 += ((const float*)&r4[idx])[k];
        }
        g_partials[((size_t)b * NBLK_ + chunk) * C_ + t] = make_float4(a1, a2, a3, a4);
    }

    // ---- last block of this batch finalizes ----
    __shared__ int is_last;
    __threadfence();
    __syncthreads();
    if (t == 0) is_last = (atomicAdd(&g_done[b], 1) == NBLK_ - 1) ? 1 : 0;
    __syncthreads();
    if (!is_last) return;

    // 256 threads: thread t<128 sums chunks 0..63 of channel t,
    // thread t>=128 sums chunks 64..127 of channel t-128.
    {
        int c    = t & 127;
        int half = t >> 7;
        const float4* pp = g_partials + (size_t)b * NBLK_ * C_ + (size_t)(half * 64) * C_ + c;
        float a1 = 0.f, a2 = 0.f, a3 = 0.f, a4 = 0.f;
        #pragma unroll 8
        for (int k = 0; k < 64; k++) {
            float4 p = pp[(size_t)k * C_];
            a1 += p.x; a2 += p.y; a3 += p.z; a4 += p.w;
        }
        r1[t] = make_float4(a1, a2, a3, a4);
    }
    __syncthreads();
    if (t < C_) {
        float4 lo = r1[t], hi = r1[t + 128];
        float s1v_ = lo.x + hi.x;
        float s2v_ = lo.y + hi.y;
        float s1_  = lo.z + hi.z;
        float s2_  = lo.w + hi.w;

        float cnt_v = (float)g_counts[b];
        float cnt_m = (float)HW_ - cnt_v;
        float s1m = s1_ - s1v_;
        float s2m = s2_ - s2v_;

        float fs_v  = cnt_v + EPS_;
        float mu_v  = s1v_ / fs_v;
        float var_v = (s2v_ - 2.f * mu_v * s1v_ + mu_v * mu_v * cnt_v) / fs_v;
        float is_v  = 1.0f / sqrtf(var_v + EPS_);
        float fs_m  = cnt_m + EPS_;
        float mu_m  = s1m / fs_m;
        float var_m = (s2m - 2.f * mu_m * s1m + mu_m * mu_m * cnt_m) / fs_m;
        float is_m  = 1.0f / sqrtf(var_m + EPS_);

        ((float2*)g_params)[((size_t)b * 2 + 1) * C_ + t] = make_float2(mu_v, is_v);
        ((float2*)g_params)[((size_t)b * 2 + 0) * C_ + t] = make_float2(mu_m, is_m);
    }
}

// ============================================================
// Kernel 4: out = (x - mu_r) * istd_r * beta + gamma
// ============================================================
__global__ void apply_kernel(const float* __restrict__ in, float* __restrict__ out) {
    int t = threadIdx.x;
    size_t base = (size_t)blockIdx.x * 1024;
    int pix0 = blockIdx.x * 32;
    int b = pix0 >> 16;

    __shared__ float4 sparams[128];   // [region(2)][c4(32)][2]
    if (t < 128) sparams[t] = ((const float4*)g_params)[b * 128 + t];
    __syncthreads();

    const float4* in4 = (const float4*)in;
    float4* out4 = (float4*)out;

    float4 v[4];
    #pragma unroll
    for (int k = 0; k < 4; k++)
        v[k] = in4[base + t + 256 * k];

    #pragma unroll
    for (int k = 0; k < 4; k++) {
        int i4  = t + 256 * k;
        int pix = pix0 + (i4 >> 5);
        int c4  = i4 & 31;
        int m        = g_mask[pix];
        float beta   = g_bmap[pix];
        float gamma  = g_gmap[pix];
        float4 p0 = sparams[m * 64 + c4 * 2];
        float4 p1 = sparams[m * 64 + c4 * 2 + 1];
        float4 o;
        o.x = (v[k].x - p0.x) * p0.y * beta + gamma;
        o.y = (v[k].y - p0.z) * p0.w * beta + gamma;
        o.z = (v[k].z - p1.x) * p1.y * beta + gamma;
        o.w = (v[k].w - p1.z) * p1.w * beta + gamma;
        out4[base + i4] = o;
    }
}

// ============================================================
extern "C" void kernel_launch(void* const* d_in, const int* in_sizes, int n_in,
                              void* d_out, int out_size) {
    const float* in      = (const float*)d_in[0];
    const float* w_sr    = (const float*)d_in[1];
    const float* b_sr    = (const float*)d_in[2];
    const float* w_gamma = (const float*)d_in[3];
    const float* b_gamma = (const float*)d_in[4];
    const float* w_beta  = (const float*)d_in[5];
    const float* b_beta  = (const float*)d_in[6];
    float* out = (float*)d_out;

    pool_kernel<<<P_ / 32, 256>>>(in);
    fused_conv_kernel<<<B_ * 64, 256>>>(w_sr, b_sr, w_gamma, b_gamma, w_beta, b_beta);
    moments_kernel<<<dim3(NBLK_, B_), 256>>>(in);
    apply_kernel<<<P_ / 32, 256>>>(in, out);
}